// round 9
// baseline (speedup 1.0000x reference)
#include <cuda_runtime.h>
#include <math.h>

#define NB 8
#define NT 8192
#define ND 2048
#define NROWS (NB * NT)
#define KSEL 2048      // NT * 0.25
#define CPB 8          // CTAs per batch in kernel 2
#define GRID2 (NB * CPB)   // 64 CTAs -> always co-resident (<= 148 SMs)
#define CAND_MAX 768

// Device-global scratch (no allocations). All counters/histograms consumed
// by kernel2 are zeroed by kernel1 each replay -> graph-replay safe.
// Spin-barrier generations are monotonic; counts self-reset.
__device__ double   d_ea[NROWS];         // exp(-bce_p * CE)   per row
__device__ double   d_eb0[NROWS];        // exp(-bcu_p * D_st) per row
__device__ double   d_part[NROWS / 8];   // per-CTA fp64 partial sums of D_st
__device__ double   d_K;                 // exp(bcu_p * m * ma)
__device__ int      d_ctr1;
__device__ unsigned d_coarse[NB * 256];     // hist on top byte of g bits
__device__ unsigned d_fine[NB * 65536];     // hist on top 16 bits
__device__ unsigned d_fh[NB * 256];         // fallback hist (byte 1)
__device__ unsigned d_fh2[NB * 256];        // fallback hist (byte 0)
__device__ unsigned d_cand[NB * CAND_MAX];  // candidate keys
__device__ unsigned d_candcnt[NB];
__device__ unsigned d_bcnt[NB * 3];         // per-batch spin barriers
__device__ unsigned d_bgen[NB * 3];

// Fast fp64 exp: Cody-Waite + 13-term poly, ~1e-15 rel err (R6/R7: final
// fp32 g bits identical to libm; ordering gaps near k-th largest are ~1e-5).
__device__ __forceinline__ double fast_exp(double x)
{
    x = fmin(fmax(x, -700.0), 700.0);
    double k = rint(x * 1.4426950408889634074);
    double r = fma(-k, 6.93147180369123816490e-01, x);
    r = fma(-k, 1.90821492927058770002e-10, r);
    double p = 2.08767569878681e-09;
    p = fma(p, r, 2.50521083854417e-08);
    p = fma(p, r, 2.75573192239859e-07);
    p = fma(p, r, 2.75573192239859e-06);
    p = fma(p, r, 2.48015873015873e-05);
    p = fma(p, r, 1.98412698412698e-04);
    p = fma(p, r, 1.38888888888889e-03);
    p = fma(p, r, 8.33333333333333e-03);
    p = fma(p, r, 4.16666666666667e-02);
    p = fma(p, r, 1.66666666666667e-01);
    p = fma(p, r, 0.5);
    p = fma(p, r, 1.0);
    p = fma(p, r, 1.0);
    return p * __longlong_as_double((unsigned long long)((long long)k + 1023) << 52);
}

// ---------------------------------------------------------------------------
// Kernel 1: per-row squared-norm reductions (warp-per-row, at the LTS/HBM
// cap: reads the full 1.07 GB and IS the runtime); per-row fp64 exps in a
// one-warp CTA tail (hidden under memory stalls); last-arriving CTA computes
// the global mean -> scalar K. Also zeroes kernel2's histograms/counters
// (one store for ~25% of threads -- free). Proven structure from R7.
// ---------------------------------------------------------------------------
__global__ void __launch_bounds__(256) row_reduce_kernel(
    const float4* __restrict__ a, const float4* __restrict__ p,
    const float* __restrict__ oce, const float* __restrict__ mcu,
    const float* __restrict__ bce, const float* __restrict__ bcu)
{
    // zero kernel2 scratch (stream order guarantees visibility to kernel2)
    {
        const unsigned gt = blockIdx.x * 256u + threadIdx.x;
        if (gt < 524288u) d_fine[gt] = 0u;
        else if (gt < 524288u + 2048u)  d_coarse[gt - 524288u] = 0u;
        else if (gt < 524288u + 4096u)  d_fh[gt - 524288u - 2048u] = 0u;
        else if (gt < 524288u + 6144u)  d_fh2[gt - 524288u - 4096u] = 0u;
        else if (gt < 524288u + 6144u + NB) d_candcnt[gt - 524288u - 6144u] = 0u;
    }

    const int warp = threadIdx.x >> 5;
    const int lane = threadIdx.x & 31;
    const int row  = blockIdx.x * 8 + warp;
    const size_t base = (size_t)row * (ND / 4);

    float s_st = 0.0f, s_ch = 0.0f;
#pragma unroll
    for (int j = 0; j < 16; ++j) {
        const size_t idx = base + lane + 32 * j;
        float4 av = __ldg(&a[idx]);
        float4 pv = __ldg(&p[idx]);
        s_st += av.x * av.x + av.y * av.y + av.z * av.z + av.w * av.w;
        float dx = av.x - pv.x, dy = av.y - pv.y;
        float dz = av.z - pv.z, dw = av.w - pv.w;
        s_ch += dx * dx + dy * dy + dz * dz + dw * dw;
    }

#pragma unroll
    for (int off = 16; off > 0; off >>= 1) {
        s_st += __shfl_down_sync(0xFFFFFFFFu, s_st, off);
        s_ch += __shfl_down_sync(0xFFFFFFFFu, s_ch, off);
    }

    __shared__ float sh_dst[8], sh_dch[8];
    if (lane == 0) {
        const float invd = 1.0f / (float)ND;
        sh_dst[warp] = s_st * invd;
        sh_dch[warp] = s_ch * invd;
    }
    __syncthreads();

    // CTA tail: 8 lanes compute the 2 fp64 exps per row + CTA partial sum.
    if (threadIdx.x < 8) {
        const float xce = bce[0], xcu = bcu[0];
        const float bce_p = fmaxf(xce, 0.0f) + log1pf(expf(-fabsf(xce)));
        const float bcu_p = fmaxf(xcu, 0.0f) + log1pf(expf(-fabsf(xcu)));
        const float logoce = logf(oce[0] + 1e-10f);

        const int r = blockIdx.x * 8 + threadIdx.x;
        const double dst = (double)sh_dst[threadIdx.x];
        const double dch = (double)sh_dch[threadIdx.x];
        const double CE = dst - (dch - (double)logoce);
        d_ea[r]  = fast_exp(-(double)bce_p * CE);
        d_eb0[r] = fast_exp(-(double)bcu_p * dst);

        if (threadIdx.x == 0) {
            double ps = 0.0;
#pragma unroll
            for (int i = 0; i < 8; ++i) ps += (double)sh_dst[i];
            d_part[blockIdx.x] = ps;
        }
    }

    // last-CTA: global mean of D_st -> scalar K
    __shared__ int s_last;
    __threadfence();
    __syncthreads();
    if (threadIdx.x == 0)
        s_last = (atomicAdd(&d_ctr1, 1) == (int)gridDim.x - 1);
    __syncthreads();
    if (!s_last) return;
    __threadfence();

    const int t = threadIdx.x;
    double a0 = 0.0, a1 = 0.0, a2 = 0.0, a3 = 0.0;
#pragma unroll
    for (int j = 0; j < 8; ++j) {
        a0 += __ldcg(&d_part[t + (4 * j + 0) * 256]);
        a1 += __ldcg(&d_part[t + (4 * j + 1) * 256]);
        a2 += __ldcg(&d_part[t + (4 * j + 2) * 256]);
        a3 += __ldcg(&d_part[t + (4 * j + 3) * 256]);
    }
    double s = (a0 + a1) + (a2 + a3);
#pragma unroll
    for (int off = 16; off > 0; off >>= 1)
        s += __shfl_down_sync(0xFFFFFFFFu, s, off);
    __shared__ double ws[8];
    if (lane == 0) ws[warp] = s;
    __syncthreads();
    if (t == 0) {
        double tot = 0.0;
#pragma unroll
        for (int i = 0; i < 8; ++i) tot += ws[i];
        const double ma = tot / (double)NROWS;
        const float xcu = bcu[0];
        const float bcu_p = fmaxf(xcu, 0.0f) + log1pf(expf(-fabsf(xcu)));
        d_K = fast_exp((double)bcu_p * (double)mcu[0] * ma);
        d_ctr1 = 0;   // reset for next graph replay
    }
}

// ---------------------------------------------------------------------------
// Per-batch spin barrier for kernel2. SAFE: grid2 = 64 CTAs < 148 SMs, so the
// whole grid is co-resident in wave 1 -- every waiter's releaser is running.
// Generation-based (monotonic), count self-resets -> graph-replay safe.
// Called by tid==0 only; caller brackets with __syncthreads().
// ---------------------------------------------------------------------------
__device__ __forceinline__ void batch_barrier(int slot)
{
    __threadfence();   // release
    const unsigned g0 = *((volatile unsigned*)&d_bgen[slot]);
    if (atomicAdd(&d_bcnt[slot], 1u) == CPB - 1) {
        d_bcnt[slot] = 0;
        __threadfence();
        atomicAdd(&d_bgen[slot], 1u);
    } else {
        while (*((volatile unsigned*)&d_bgen[slot]) == g0) __nanosleep(64);
    }
    __threadfence();   // acquire
}

// Suffix-scan a 256-bin global histogram and pick the bin where the running
// top-down count crosses remk. Threads t<256 participate (8 warps); winner
// writes (bin, rem-within-bin, bin-count) to smem. Deterministic.
__device__ __forceinline__ void suffix_pick(
    const unsigned* __restrict__ bins, int remk,
    int tid, int lane, int warp, int* s_wt,
    int* s_bin, int* s_rem, int* s_cnt)
{
    int v = 0, x = 0;
    if (tid < 256) {
        v = (int)__ldcg(&bins[255 - tid]);   // thread t owns bin 255-t
        x = v;
#pragma unroll
        for (int off = 1; off < 32; off <<= 1) {
            const int y = __shfl_up_sync(0xFFFFFFFFu, x, off);
            if (lane >= off) x += y;
        }
        if (lane == 31) s_wt[warp] = x;
    }
    __syncthreads();
    if (tid < 256) {
        int offset = 0;
        for (int w = 0; w < warp; ++w) offset += s_wt[w];
        const int cum  = x + offset;   // keys in bins >= mine
        const int prev = cum - v;      // keys in bins  > mine
        if (prev < remk && cum >= remk) {   // exactly one winner
            *s_bin = 255 - tid;
            *s_rem = remk - prev;
            *s_cnt = v;
        }
    }
    __syncthreads();
}

// ---------------------------------------------------------------------------
// Kernel 2: 64 CTAs x 1024 threads, one g element per thread. Gate (Newton-
// recip fp64, bit-stable vs R6/R7) + global-atomic coarse/fine histograms,
// then per-batch cooperative exact top-k: every CTA redundantly scans two
// 1 KB histograms, candidates gathered globally and rank-counted, each
// thread writes its own mask element. No single-CTA serial phase remains
// (R3-R7 evidence: that serial phase was a constant ~16us regardless of
// instruction mix). Exact multi-round fallback for heavy threshold bins.
// ---------------------------------------------------------------------------
__global__ void __launch_bounds__(1024) gate_select_kernel(float* __restrict__ out)
{
    __shared__ int s_wt[8];
    __shared__ int s_B, s_rem1, s_lo, s_rem2, s_cbin;
    __shared__ int s_b1, s_rem3, s_dum;
    __shared__ int s_b0, s_need0, s_ceq0;
    __shared__ unsigned s_cand[CAND_MAX];
    __shared__ unsigned s_thresh;
    __shared__ int s_need, s_ceq;

    const int cta  = blockIdx.x;
    const int b    = cta >> 3;          // batch
    const int seg  = cta & 7;
    const int tid  = threadIdx.x;
    const int warp = tid >> 5;
    const int lane = tid & 31;
    const int i    = seg * 1024 + tid;  // index within batch
    const int gidx = b * NT + i;

    // ---- gate: one element per thread ----
    unsigned u;
    {
        const double K    = d_K;
        const double ea   = __ldcg(&d_ea[gidx]);
        const double eb   = __ldcg(&d_eb0[gidx]) * K;
        const double num  = 1.0 + ea + eb;
        const double den  = num + ea * eb;
        double rcp = (double)__frcp_rn((float)den);
        rcp = fma(fma(-den, rcp, 1.0), rcp, rcp);   // Newton 1
        rcp = fma(fma(-den, rcp, 1.0), rcp, rcp);   // Newton 2 -> ~0.5 ulp
        const float g = (float)(num * rcp);
        out[gidx] = g;
        u = __float_as_uint(g);   // g in (0,1): uint order == float order
    }

    // histograms (RED, no return): coarse on byte3, fine on top 16 bits
    atomicAdd(&d_coarse[b * 256 + (u >> 24)], 1u);
    atomicAdd(&d_fine[b * 65536 + (u >> 16)], 1u);

    // ---- barrier 0: all 8 CTAs of this batch have gated + histogrammed ----
    __syncthreads();
    if (tid == 0) batch_barrier(b * 3 + 0);
    __syncthreads();

    // ---- redundant (per-CTA) coarse then fine scan -> 16-bit prefix ----
    suffix_pick(d_coarse + b * 256, KSEL, tid, lane, warp, s_wt,
                &s_B, &s_rem1, &s_dum);
    suffix_pick(d_fine + b * 65536 + s_B * 256, s_rem1, tid, lane, warp, s_wt,
                &s_lo, &s_rem2, &s_cbin);

    const unsigned prefix = ((unsigned)s_B << 8) | (unsigned)s_lo;  // top 16 bits
    const int remk2 = s_rem2;
    const int cbin  = s_cbin;

    if (cbin <= CAND_MAX) {
        // ---- gather candidates globally, rank-count exact threshold ----
        if ((u >> 16) == prefix) {
            const unsigned pos = atomicAdd(&d_candcnt[b], 1u);
            d_cand[b * CAND_MAX + pos] = u;
        }
        __syncthreads();
        if (tid == 0) batch_barrier(b * 3 + 1);
        __syncthreads();

        const int c2 = (int)*((volatile unsigned*)&d_candcnt[b]);  // == cbin
        if (tid < c2) s_cand[tid] = __ldcg(&d_cand[b * CAND_MAX + tid]);
        __syncthreads();
        if (tid < c2) {
            const unsigned vi = s_cand[tid];
            int greater = 0, equal = 0;
            for (int j = 0; j < c2; ++j) {
                const unsigned vj = s_cand[j];
                greater += (vj > vi);
                equal   += (vj == vi);
            }
            // order-independent -> deterministic; duplicate winners benign
            if (greater < remk2 && remk2 <= greater + equal) {
                s_thresh = vi; s_need = remk2 - greater; s_ceq = equal;
            }
        }
        __syncthreads();
    } else {
        // ---- exact fallback: two more global-atomic byte rounds ----
        if ((u >> 16) == prefix)
            atomicAdd(&d_fh[b * 256 + ((u >> 8) & 0xFFu)], 1u);
        __syncthreads();
        if (tid == 0) batch_barrier(b * 3 + 1);
        __syncthreads();
        suffix_pick(d_fh + b * 256, remk2, tid, lane, warp, s_wt,
                    &s_b1, &s_rem3, &s_dum);

        const unsigned pref24 = (prefix << 8) | (unsigned)s_b1;
        if ((u >> 8) == pref24)
            atomicAdd(&d_fh2[b * 256 + (u & 0xFFu)], 1u);
        __syncthreads();
        if (tid == 0) batch_barrier(b * 3 + 2);
        __syncthreads();
        suffix_pick(d_fh2 + b * 256, s_rem3, tid, lane, warp, s_wt,
                    &s_b0, &s_need0, &s_ceq0);
        if (tid == 0) {
            s_thresh = (pref24 << 8) | (unsigned)s_b0;
            s_need   = s_need0;
            s_ceq    = s_ceq0;
        }
        __syncthreads();
    }

    const unsigned thresh = s_thresh;   // exact bit pattern of k-th largest
    const int need_eq = s_need;
    const int c_eq    = s_ceq;

    // ---- mask write: each thread its own element ----
    float mval;
    if (u > thresh)      mval = 1.0f;
    else if (u < thresh) mval = 0.0f;
    else if (c_eq == need_eq) mval = 1.0f;     // no over-tie (common)
    else {
        // rare exact fp32 tie: lower index wins (jax.lax.top_k)
        const float* gb = out + b * NT;
        int rnk = 0;
        for (int j = 0; j < i; ++j)
            if (__float_as_uint(__ldcg(&gb[j])) == thresh) ++rnk;
        mval = (rnk < need_eq) ? 1.0f : 0.0f;
    }
    out[NROWS + gidx] = mval;
}

// ---------------------------------------------------------------------------
extern "C" void kernel_launch(void* const* d_in, const int* in_sizes, int n_in,
                              void* d_out, int out_size)
{
    const float4* a = (const float4*)d_in[0];   // actual_residual   [8,8192,2048] f32
    const float4* p = (const float4*)d_in[1];   // predicted_residual[8,8192,2048] f32
    const float* oce = (const float*)d_in[2];
    const float* mcu = (const float*)d_in[3];
    const float* bce = (const float*)d_in[4];
    const float* bcu = (const float*)d_in[5];
    float* out = (float*)d_out;                  // [2, 8, 8192]: g then binary mask

    row_reduce_kernel<<<NROWS / 8, 256>>>(a, p, oce, mcu, bce, bcu);
    gate_select_kernel<<<GRID2, 1024>>>(out);
}